// round 6
// baseline (speedup 1.0000x reference)
#include <cuda_runtime.h>
#include <cuda_bf16.h>
#include <cstdint>
#include <cstddef>

// Problem constants
#define BB   4
#define NBL  256
#define LQ   64
#define KK_  65
#define CC   512
#define HH   8
#define HDIM 64
#define SCALE 0.125f
#define THREE_C 1536

// ---------------- scratch (static device globals: allocation-free) ----------------
__device__ float g_bmean[(size_t)BB * NBL * CC];                   //   2 MB
__device__ float g_Q    [(size_t)BB * NBL * LQ * CC];              // 134 MB
__device__ float g_KV   [(size_t)BB * NBL * KK_ * 2 * CC];         // 272 MB
__device__ float g_O    [(size_t)BB * NBL * LQ * CC];              // 134 MB
__device__ int   g_mask_mode;                                      // 0=u8, 1=i32, 2=f32

// ---------------- mask dtype detection ----------------
// bool(u8): nonzero bytes at idx%4==1.  int32 0/1: nonzero only at idx%4==0.
// float32 0/1.0f: LE bytes 00 00 80 3F -> positions 0 and 1 both zero.
__global__ void detect_mask_kernel(const unsigned char* __restrict__ m) {
    __shared__ int sA, s0;
    if (threadIdx.x == 0) { sA = 0; s0 = 0; }
    __syncthreads();
    int a = 0, z = 0;
    for (int i = threadIdx.x; i < 4096; i += blockDim.x) {
        int v = m[i];
        if ((i & 3) == 1) a |= v;
        if ((i & 3) == 0) z |= v;
    }
    if (a) atomicOr(&sA, 1);
    if (z) atomicOr(&s0, 1);
    __syncthreads();
    if (threadIdx.x == 0) g_mask_mode = sA ? 0 : (s0 ? 1 : 2);
}

// ---------------- block mean ----------------
__global__ void block_mean_kernel(const float* __restrict__ x, float* __restrict__ bm) {
    int blk = blockIdx.x;       // b*NBL + nb
    int c   = threadIdx.x;      // 0..511
    const float* base = x + (size_t)blk * LQ * CC + c;
    float s = 0.f;
#pragma unroll
    for (int l = 0; l < LQ; l++) s += base[(size_t)l * CC];
    bm[(size_t)blk * CC + c] = s * (1.0f / 64.0f);
}

// ---------------- generic tiled SGEMM: Cout = gather(A) @ W[:, wcol0:wcol0+N] + bias ----
// BM=128, BN=64, BK=16, 256 threads, 8x4 per-thread tile. Exact-multiple shapes only.
__device__ __forceinline__ const float* a_row_ptr(const float* __restrict__ A,
                                                  const float* __restrict__ bmean,
                                                  int mode, int r) {
    if (mode == 0) return A + (size_t)r * CC;
    // kv gather: row r of (B, NB, K=65) -> x row or block-mean row
    int b  = r / (NBL * KK_);
    int t  = r - b * (NBL * KK_);
    int nb = t / KK_;
    int kk = t - nb * KK_;
    if (kk < LQ) return A + ((size_t)(b * NBL + nb) * LQ + kk) * CC;
    return bmean + (size_t)(b * NBL + nb) * CC;
}

__global__ __launch_bounds__(256) void gemm_kernel(
    const float* __restrict__ A, const float* __restrict__ bmean, int gmode,
    const float* __restrict__ W, int ldw, int wcol0,
    const float* __restrict__ bias, int bias0,
    float* __restrict__ Cout, int ldc, int Kdim)
{
    __shared__ float As[16][128];
    __shared__ float Bs[16][64];

    const int tid = threadIdx.x;
    const int tx  = tid & 15;          // N dim (x4)
    const int ty  = tid >> 4;          // M dim (x8)
    const int rowBase = blockIdx.y * 128;
    const int colBase = blockIdx.x * 64;

    // A loader mapping: thread loads 2 float4s: (row=tid/4, col4=(tid&3)*4) and row+64
    const int lr0 = tid >> 2;
    const int lc4 = (tid & 3) * 4;
    const float* pA0 = a_row_ptr(A, bmean, gmode, rowBase + lr0);
    const float* pA1 = a_row_ptr(A, bmean, gmode, rowBase + lr0 + 64);

    // W loader mapping: row = tid/16, col4 = (tid&15)*4  (columns relative to this block)
    const int wr  = tid >> 4;
    const int wc4 = (tid & 15) * 4;
    // FIX: include colBase in the weight column offset (was missing -> all column
    // blocks used block 0's weight columns -> rel_err ~ sqrt(2)).
    const float* pW = W + (size_t)wr * ldw + wcol0 + colBase + wc4;

    float acc[8][4];
#pragma unroll
    for (int i = 0; i < 8; i++)
#pragma unroll
        for (int j = 0; j < 4; j++) acc[i][j] = 0.f;

    for (int k0 = 0; k0 < Kdim; k0 += 16) {
        float4 a0 = *(const float4*)(pA0 + k0 + lc4);
        float4 a1 = *(const float4*)(pA1 + k0 + lc4);
        float4 bv = *(const float4*)(pW + (size_t)k0 * ldw);

        __syncthreads();   // previous tile fully consumed
        As[lc4 + 0][lr0] = a0.x; As[lc4 + 1][lr0] = a0.y;
        As[lc4 + 2][lr0] = a0.z; As[lc4 + 3][lr0] = a0.w;
        As[lc4 + 0][lr0 + 64] = a1.x; As[lc4 + 1][lr0 + 64] = a1.y;
        As[lc4 + 2][lr0 + 64] = a1.z; As[lc4 + 3][lr0 + 64] = a1.w;
        *(float4*)&Bs[wr][wc4] = bv;
        __syncthreads();

#pragma unroll
        for (int kk = 0; kk < 16; kk++) {
            float4 av0 = *(const float4*)&As[kk][ty * 8];
            float4 av1 = *(const float4*)&As[kk][ty * 8 + 4];
            float4 bb  = *(const float4*)&Bs[kk][tx * 4];
            float ar[8] = {av0.x, av0.y, av0.z, av0.w, av1.x, av1.y, av1.z, av1.w};
            float br[4] = {bb.x, bb.y, bb.z, bb.w};
#pragma unroll
            for (int i = 0; i < 8; i++)
#pragma unroll
                for (int j = 0; j < 4; j++)
                    acc[i][j] = fmaf(ar[i], br[j], acc[i][j]);
        }
    }

#pragma unroll
    for (int i = 0; i < 8; i++) {
        int r = rowBase + ty * 8 + i;
#pragma unroll
        for (int j = 0; j < 4; j++) {
            int c = colBase + tx * 4 + j;
            Cout[(size_t)r * ldc + c] = acc[i][j] + bias[bias0 + c];
        }
    }
}

// ---------------- fused per-(b,nb,h) attention ----------------
// smem: Qs[64*64] + Ks[65*65] + Vs[65*65] + S[64*65]  (stride-65 K/V rows: conflict-free)
#define ATTN_SMEM_FLOATS (64 * 64 + 65 * 65 + 65 * 65 + 64 * 65)

__global__ __launch_bounds__(256) void attn_kernel(
    const float* __restrict__ Qb, const float* __restrict__ KVb,
    const float* __restrict__ edge, const void* __restrict__ maskp,
    float* __restrict__ Ob)
{
    extern __shared__ float sm[];
    float* Qs = sm;                 // [64][64]
    float* Ks = Qs + 64 * 64;       // [65][65] (only 64 cols used)
    float* Vs = Ks + 65 * 65;       // [65][65]
    float* S  = Vs + 65 * 65;       // [64][65]

    const int h  = blockIdx.x;
    const int nb = blockIdx.y;
    const int b  = blockIdx.z;
    const int tid = threadIdx.x;
    const size_t bn = (size_t)b * NBL + nb;

    for (int idx = tid; idx < 64 * 64; idx += 256) {
        int l = idx >> 6, d = idx & 63;
        Qs[idx] = Qb[(bn * 64 + l) * 512 + h * 64 + d];
    }
    for (int idx = tid; idx < 65 * 64; idx += 256) {
        int kk = idx >> 6, d = idx & 63;
        size_t rb = (bn * 65 + kk) * 1024 + h * 64 + d;
        Ks[kk * 65 + d] = KVb[rb];
        Vs[kk * 65 + d] = KVb[rb + 512];
    }
    __syncthreads();

    const int mode = g_mask_mode;

    // scores + bias + mask
    for (int idx = tid; idx < 64 * 65; idx += 256) {
        int l  = idx / 65;
        int kk = idx - l * 65;
        const float* q  = Qs + l * 64;
        const float* kp = Ks + kk * 65;
        float s = 0.f;
#pragma unroll
        for (int d = 0; d < 64; d++) s = fmaf(q[d], kp[d], s);
        s *= SCALE;

        float bias;
        if (kk == 64 || kk == l) bias = 1.0f;
        else bias = edge[((((size_t)nb * 64) + l) * 65 + kk) * 4 + 3];
        s += bias;

        size_t mi = ((size_t)nb * 64 + l) * 65 + kk;
        bool ok;
        if (mode == 0)      ok = ((const unsigned char*)maskp)[mi] != 0;
        else if (mode == 1) ok = ((const int*)maskp)[mi] != 0;
        else                ok = ((const float*)maskp)[mi] != 0.0f;

        S[l * 65 + kk] = ok ? s : -1.0e9f;
    }
    __syncthreads();

    // softmax: one warp per row
    const int w = tid >> 5, lane = tid & 31;
    for (int r = w; r < 64; r += 8) {
        float mx = -1.0e30f;
        for (int kk = lane; kk < 65; kk += 32) mx = fmaxf(mx, S[r * 65 + kk]);
#pragma unroll
        for (int off = 16; off; off >>= 1) mx = fmaxf(mx, __shfl_xor_sync(0xffffffffu, mx, off));
        float sum = 0.f;
        for (int kk = lane; kk < 65; kk += 32) sum += __expf(S[r * 65 + kk] - mx);
#pragma unroll
        for (int off = 16; off; off >>= 1) sum += __shfl_xor_sync(0xffffffffu, sum, off);
        float inv = 1.0f / sum;
        for (int kk = lane; kk < 65; kk += 32)
            S[r * 65 + kk] = __expf(S[r * 65 + kk] - mx) * inv;
    }
    __syncthreads();

    // out = S @ V
    for (int idx = tid; idx < 64 * 64; idx += 256) {
        int l = idx >> 6, d = idx & 63;
        const float* sp = S + l * 65;
        const float* vp = Vs + d;
        float s = 0.f;
#pragma unroll
        for (int kk = 0; kk < 65; kk++) s = fmaf(sp[kk], vp[kk * 65], s);
        Ob[(bn * 64 + l) * 512 + h * 64 + d] = s;
    }
}

// ---------------- launch ----------------
extern "C" void kernel_launch(void* const* d_in, const int* in_sizes, int n_in,
                              void* d_out, int out_size) {
    // Bind inputs by ELEMENT COUNT (all seven are distinct) — robust to any
    // metadata ordering:
    //   x          4*16384*512   = 33554432
    //   attn_mask  256*64*65     = 1064960
    //   edge_feats 256*64*65*4   = 4259840
    //   qkv_w      512*1536      = 786432
    //   qkv_b                    = 1536
    //   proj_w     512*512       = 262144
    //   proj_b                   = 512
    const float *x = 0, *edge = 0, *qkv_w = 0, *qkv_b = 0, *proj_w = 0, *proj_b = 0;
    const void  *mask = 0;
    for (int i = 0; i < n_in; i++) {
        switch (in_sizes[i]) {
            case 33554432: x      = (const float*)d_in[i]; break;
            case 1064960:  mask   = d_in[i];               break;
            case 4259840:  edge   = (const float*)d_in[i]; break;
            case 786432:   qkv_w  = (const float*)d_in[i]; break;
            case 1536:     qkv_b  = (const float*)d_in[i]; break;
            case 262144:   proj_w = (const float*)d_in[i]; break;
            case 512:      proj_b = (const float*)d_in[i]; break;
            default: break;
        }
    }
    float* out = (float*)d_out;

    float *bmean, *Q, *KV, *O;
    cudaGetSymbolAddress((void**)&bmean, g_bmean);
    cudaGetSymbolAddress((void**)&Q,     g_Q);
    cudaGetSymbolAddress((void**)&KV,    g_KV);
    cudaGetSymbolAddress((void**)&O,     g_O);

    cudaFuncSetAttribute(attn_kernel, cudaFuncAttributeMaxDynamicSharedMemorySize,
                         ATTN_SMEM_FLOATS * (int)sizeof(float));

    // 0. detect mask dtype (deterministic function of input bytes)
    detect_mask_kernel<<<1, 256>>>((const unsigned char*)mask);

    // 1. block means
    block_mean_kernel<<<BB * NBL, CC>>>(x, bmean);

    // 2. Q = x @ qkv_w[:, 0:512] + qkv_b[0:512]      (M=65536, N=512, K=512)
    gemm_kernel<<<dim3(512 / 64, (BB * NBL * LQ) / 128), 256>>>(
        x, bmean, 0, qkv_w, THREE_C, 0, qkv_b, 0, Q, CC, CC);

    // 3. KV = gather(kv) @ qkv_w[:, 512:1536] + qkv_b[512:1536]  (M=66560, N=1024, K=512)
    gemm_kernel<<<dim3(1024 / 64, (BB * NBL * KK_) / 128), 256>>>(
        x, bmean, 1, qkv_w, THREE_C, 512, qkv_b, 512, KV, 2 * CC, CC);

    // 4. attention per (b, nb, h)
    attn_kernel<<<dim3(HH, NBL, BB), 256, ATTN_SMEM_FLOATS * sizeof(float)>>>(
        Q, KV, edge, mask, O);

    // 5. out = O @ proj_w + proj_b                    (M=65536, N=512, K=512)
    gemm_kernel<<<dim3(512 / 64, (BB * NBL * LQ) / 128), 256>>>(
        O, bmean, 0, proj_w, CC, 0, proj_b, 0, out, CC, CC);
}

// round 8
// speedup vs baseline: 1.6443x; 1.6443x over previous
#include <cuda_runtime.h>
#include <cuda_bf16.h>
#include <cstdint>
#include <cstddef>

// Problem constants
#define BB   4
#define NBL  256
#define LQ   64
#define KK_  65
#define CC   512
#define HH   8
#define SCALE 0.125f
#define THREE_C 1536

// ---------------- scratch (static device globals: allocation-free) ----------------
__device__ __align__(128) __nv_bfloat16 g_xh[(size_t)BB * NBL * LQ * CC];     // 67MB
__device__ __align__(128) __nv_bfloat16 g_xl[(size_t)BB * NBL * LQ * CC];     // 67MB
__device__ __align__(128) float         g_bmean[(size_t)BB * NBL * CC];       //  2MB
__device__ __align__(128) __nv_bfloat16 g_bmh[(size_t)BB * NBL * CC];
__device__ __align__(128) __nv_bfloat16 g_bml[(size_t)BB * NBL * CC];
__device__ __align__(128) __nv_bfloat16 g_wqh[(size_t)CC * THREE_C];          // [K=512][1536]
__device__ __align__(128) __nv_bfloat16 g_wql[(size_t)CC * THREE_C];
__device__ __align__(128) __nv_bfloat16 g_wph[(size_t)CC * CC];               // [512][512]
__device__ __align__(128) __nv_bfloat16 g_wpl[(size_t)CC * CC];
__device__ __align__(128) float         g_Q [(size_t)BB * NBL * LQ * CC];     // 134MB
__device__ __align__(128) float         g_KV[(size_t)BB * NBL * KK_ * 2 * CC];// 272MB
__device__ __align__(128) __nv_bfloat16 g_Oh[(size_t)BB * NBL * LQ * CC];     // 67MB
__device__ __align__(128) __nv_bfloat16 g_Ol[(size_t)BB * NBL * LQ * CC];     // 67MB
__device__ int g_mask_mode;

// ================= PTX helpers (all baseline compute_80-era, no 'a' features) ===
__device__ __forceinline__ uint32_t smem_u32(const void* p) {
    uint32_t a;
    asm("{ .reg .u64 t; cvta.to.shared.u64 t, %1; cvt.u32.u64 %0, t; }" : "=r"(a) : "l"(p));
    return a;
}
#define CP16(d, s)   asm volatile("cp.async.cg.shared.global [%0], [%1], 16;" :: "r"(d), "l"(s))
#define CP_COMMIT()  asm volatile("cp.async.commit_group;" ::: "memory")
#define CP_WAIT2()   asm volatile("cp.async.wait_group 2;" ::: "memory")

#define LDSM4(d, addr)                                                           \
    asm volatile("ldmatrix.sync.aligned.m8n8.x4.shared.b16 {%0,%1,%2,%3}, [%4];" \
        : "=r"((d)[0]), "=r"((d)[1]), "=r"((d)[2]), "=r"((d)[3]) : "r"(addr))
#define LDSM4T(d, addr)                                                          \
    asm volatile("ldmatrix.sync.aligned.m8n8.x4.trans.shared.b16 {%0,%1,%2,%3}, [%4];" \
        : "=r"((d)[0]), "=r"((d)[1]), "=r"((d)[2]), "=r"((d)[3]) : "r"(addr))

#define MMA16816(acc, a, b)                                                      \
    asm volatile("mma.sync.aligned.m16n8k16.row.col.f32.bf16.bf16.f32 "          \
        "{%0,%1,%2,%3}, {%4,%5,%6,%7}, {%8,%9}, {%0,%1,%2,%3};"                  \
        : "+f"((acc)[0]), "+f"((acc)[1]), "+f"((acc)[2]), "+f"((acc)[3])         \
        : "r"((a)[0]), "r"((a)[1]), "r"((a)[2]), "r"((a)[3]),                    \
          "r"((b)[0]), "r"((b)[1]))

// ================= small kernels =================
__global__ void detect_mask_kernel(const unsigned char* __restrict__ m) {
    __shared__ int sA, s0;
    if (threadIdx.x == 0) { sA = 0; s0 = 0; }
    __syncthreads();
    int a = 0, z = 0;
    for (int i = threadIdx.x; i < 4096; i += blockDim.x) {
        int v = m[i];
        if ((i & 3) == 1) a |= v;
        if ((i & 3) == 0) z |= v;
    }
    if (a) atomicOr(&sA, 1);
    if (z) atomicOr(&s0, 1);
    __syncthreads();
    if (threadIdx.x == 0) g_mask_mode = sA ? 0 : (s0 ? 1 : 2);
}

__global__ void block_mean_kernel(const float* __restrict__ x, float* __restrict__ bm) {
    int blk = blockIdx.x, c = threadIdx.x;
    const float* base = x + (size_t)blk * LQ * CC + c;
    float s = 0.f;
#pragma unroll
    for (int l = 0; l < LQ; l++) s += base[(size_t)l * CC];
    bm[(size_t)blk * CC + c] = s * (1.0f / 64.0f);
}

// fp32 -> bf16 hi + bf16 lo (elementwise; also used for weights, layout preserved)
__global__ void split_kernel(const float* __restrict__ src,
                             __nv_bfloat16* __restrict__ dh,
                             __nv_bfloat16* __restrict__ dl, size_t n) {
    size_t i = (size_t)blockIdx.x * blockDim.x + threadIdx.x;
    if (i >= n) return;
    float v = src[i];
    __nv_bfloat16 h = __float2bfloat16(v);
    dh[i] = h;
    dl[i] = __float2bfloat16(v - __bfloat162float(h));
}

// ================= mma.sync GEMM =================
// C[M,N] = split(A)[M,512] @ split(W)[512, wcol0:wcol0+N] + bias, 3-product bf16 compensation.
// CTA 128x128, 8 warps (2m x 4n), warp tile 64x32. K chunks of 32, 3-stage cp.async.
#define KCHUNK     32
#define NCHUNK     16                     // 512 / 32
#define A_STRIDE_B 80                     // 40 bf16 per A smem row
#define B_STRIDE_B 272                    // 136 bf16 per B smem row
#define A_HALF     10240                  // 128 * 80
#define B_HALF     8704                   // 32 * 272
#define B_OFF      20480                  // 2 * A_HALF
#define STAGE_BYTES 37888                 // 2*A_HALF + 2*B_HALF
#define GEMM_SMEM  (3 * STAGE_BYTES)      // 113664

__device__ __forceinline__ void a_ptrs(
    const __nv_bfloat16* __restrict__ Ah, const __nv_bfloat16* __restrict__ Al,
    const __nv_bfloat16* __restrict__ bmh, const __nv_bfloat16* __restrict__ bml,
    int gmode, int gr,
    const __nv_bfloat16*& ph, const __nv_bfloat16*& pl)
{
    if (gmode == 0) { size_t o = (size_t)gr * CC; ph = Ah + o; pl = Al + o; return; }
    int b  = gr / (NBL * KK_);
    int t  = gr - b * (NBL * KK_);
    int nb = t / KK_;
    int kk = t - nb * KK_;
    if (kk < LQ) { size_t o = ((size_t)(b * NBL + nb) * LQ + kk) * CC; ph = Ah + o; pl = Al + o; }
    else         { size_t o = (size_t)(b * NBL + nb) * CC;             ph = bmh + o; pl = bml + o; }
}

__global__ __launch_bounds__(256) void gemm_mma(
    const __nv_bfloat16* __restrict__ Ah, const __nv_bfloat16* __restrict__ Al,
    const __nv_bfloat16* __restrict__ bmh, const __nv_bfloat16* __restrict__ bml,
    int gmode,
    const __nv_bfloat16* __restrict__ Bh, const __nv_bfloat16* __restrict__ Bl,
    int ldB, int wcol0,
    const float* __restrict__ bias,
    float* __restrict__ C, int ldc)
{
    extern __shared__ __align__(128) char smem[];
    const uint32_t sb = smem_u32(smem);
    const int tid = threadIdx.x, wid = tid >> 5, lane = tid & 31;
    const int warp_m = wid >> 2, warp_n = wid & 3;
    const int rowBase = blockIdx.y * 128;
    const int colBase = blockIdx.x * 128;
    const int colOff  = wcol0 + colBase;   // B fetch column offset
    const int g = lane >> 3, r = lane & 7;

    float acc[4][4][4];
#pragma unroll
    for (int ma = 0; ma < 4; ma++)
#pragma unroll
        for (int na = 0; na < 4; na++)
#pragma unroll
            for (int q = 0; q < 4; q++) acc[ma][na][q] = 0.f;

    // ldmatrix per-thread address components (within a stage)
    const uint32_t aOff = (uint32_t)((warp_m * 64 + (g & 1) * 8 + r) * A_STRIDE_B + (g >> 1) * 16);
    const uint32_t bOff = (uint32_t)(B_OFF + ((g & 1) * 8 + r) * B_STRIDE_B
                                     + (warp_n * 32 + (g >> 1) * 8) * 2);

    // ---- chunk loader: fills one stage with cp.async (A hi/lo + B hi/lo) ----
    auto load_chunk = [&](int k0, uint32_t stBase) {
        // A: 128 rows x 32 bf16 (64B) = 4 x 16B per row, hi & lo
#pragma unroll
        for (int i = tid; i < 512; i += 256) {
            int row = i >> 2, seg = i & 3;
            const __nv_bfloat16 *ph, *pl;
            a_ptrs(Ah, Al, bmh, bml, gmode, rowBase + row, ph, pl);
            uint32_t da = stBase + row * A_STRIDE_B + seg * 16;
            CP16(da,          ph + k0 + seg * 8);
            CP16(da + A_HALF, pl + k0 + seg * 8);
        }
        // B: 32 rows x 128 bf16 (256B) = 16 x 16B per row, hi & lo
#pragma unroll
        for (int i = tid; i < 512; i += 256) {
            int row = i >> 4, seg = i & 15;
            size_t off = (size_t)(k0 + row) * ldB + colOff + seg * 8;
            uint32_t db = stBase + B_OFF + row * B_STRIDE_B + seg * 16;
            CP16(db,          Bh + off);
            CP16(db + B_HALF, Bl + off);
        }
    };

    // prologue: stages 0..2
#pragma unroll
    for (int s = 0; s < 3; s++) {
        load_chunk(s * KCHUNK, sb + s * STAGE_BYTES);
        CP_COMMIT();
    }

    for (int c = 0; c < NCHUNK; c++) {
        CP_WAIT2();
        __syncthreads();
        const uint32_t st = sb + (c % 3) * STAGE_BYTES;

#pragma unroll
        for (int ks = 0; ks < 2; ks++) {
            uint32_t ah[4][4], al[4][4], bh[2][4], bl[2][4];
#pragma unroll
            for (int ma = 0; ma < 4; ma++) {
                uint32_t ad = st + aOff + ma * (16 * A_STRIDE_B) + ks * 32;
                LDSM4(ah[ma], ad);
                LDSM4(al[ma], ad + A_HALF);
            }
#pragma unroll
            for (int p = 0; p < 2; p++) {
                uint32_t bd = st + bOff + ks * (16 * B_STRIDE_B) + p * 32;
                LDSM4T(bh[p], bd);
                LDSM4T(bl[p], bd + B_HALF);
            }
#pragma unroll
            for (int ma = 0; ma < 4; ma++)
#pragma unroll
                for (int na = 0; na < 4; na++) {
                    int p = na >> 1, q = (na & 1) * 2;
                    MMA16816(acc[ma][na], ah[ma], bh[p] + q);
                    MMA16816(acc[ma][na], al[ma], bh[p] + q);
                    MMA16816(acc[ma][na], ah[ma], bl[p] + q);
                }
        }
        __syncthreads();
        if (c + 3 < NCHUNK) load_chunk((c + 3) * KCHUNK, st);
        CP_COMMIT();   // keep group count aligned even when nothing issued
    }

    // epilogue: direct STG with bias (32B-coalesced per lane quad)
#pragma unroll
    for (int ma = 0; ma < 4; ma++) {
        int gr = rowBase + warp_m * 64 + ma * 16 + (lane >> 2);
#pragma unroll
        for (int na = 0; na < 4; na++) {
            int gc = colBase + warp_n * 32 + na * 8 + 2 * (lane & 3);
            float b0 = bias[gc], b1 = bias[gc + 1];
            float2 v0 = make_float2(acc[ma][na][0] + b0, acc[ma][na][1] + b1);
            float2 v1 = make_float2(acc[ma][na][2] + b0, acc[ma][na][3] + b1);
            *(float2*)&C[(size_t)gr * ldc + gc]       = v0;
            *(float2*)&C[(size_t)(gr + 8) * ldc + gc] = v1;
        }
    }
}

// ================= fused per-(b,nb,h) attention (fp32, outputs bf16 hi/lo) ========
#define ATTN_SMEM_FLOATS (64 * 64 + 65 * 65 + 65 * 65 + 64 * 65)

__global__ __launch_bounds__(256) void attn_kernel(
    const float* __restrict__ Qb, const float* __restrict__ KVb,
    const float* __restrict__ edge, const void* __restrict__ maskp,
    __nv_bfloat16* __restrict__ Oh, __nv_bfloat16* __restrict__ Ol)
{
    extern __shared__ float sm[];
    float* Qs = sm;
    float* Ks = Qs + 64 * 64;
    float* Vs = Ks + 65 * 65;
    float* S  = Vs + 65 * 65;

    const int h  = blockIdx.x;
    const int nb = blockIdx.y;
    const int b  = blockIdx.z;
    const int tid = threadIdx.x;
    const size_t bn = (size_t)b * NBL + nb;

    for (int idx = tid; idx < 64 * 64; idx += 256) {
        int l = idx >> 6, d = idx & 63;
        Qs[idx] = Qb[(bn * 64 + l) * 512 + h * 64 + d];
    }
    for (int idx = tid; idx < 65 * 64; idx += 256) {
        int kk = idx >> 6, d = idx & 63;
        size_t rb = (bn * 65 + kk) * 1024 + h * 64 + d;
        Ks[kk * 65 + d] = KVb[rb];
        Vs[kk * 65 + d] = KVb[rb + 512];
    }
    __syncthreads();

    const int mode = g_mask_mode;

    for (int idx = tid; idx < 64 * 65; idx += 256) {
        int l  = idx / 65;
        int kk = idx - l * 65;
        const float* q  = Qs + l * 64;
        const float* kp = Ks + kk * 65;
        float s = 0.f;
#pragma unroll
        for (int d = 0; d < 64; d++) s = fmaf(q[d], kp[d], s);
        s *= SCALE;

        float bias;
        if (kk == 64 || kk == l) bias = 1.0f;
        else bias = edge[((((size_t)nb * 64) + l) * 65 + kk) * 4 + 3];
        s += bias;

        size_t mi = ((size_t)nb * 64 + l) * 65 + kk;
        bool ok;
        if (mode == 0)      ok = ((const unsigned char*)maskp)[mi] != 0;
        else if (mode == 1) ok = ((const int*)maskp)[mi] != 0;
        else                ok = ((const float*)maskp)[mi] != 0.0f;

        S[l * 65 + kk] = ok ? s : -1.0e9f;
    }
    __syncthreads();

    const int w = tid >> 5, lane = tid & 31;
    for (int rr = w; rr < 64; rr += 8) {
        float mx = -1.0e30f;
        for (int kk = lane; kk < 65; kk += 32) mx = fmaxf(mx, S[rr * 65 + kk]);
#pragma unroll
        for (int off = 16; off; off >>= 1) mx = fmaxf(mx, __shfl_xor_sync(0xffffffffu, mx, off));
        float sum = 0.f;
        for (int kk = lane; kk < 65; kk += 32) sum += __expf(S[rr * 65 + kk] - mx);
#pragma unroll
        for (int off = 16; off; off >>= 1) sum += __shfl_xor_sync(0xffffffffu, sum, off);
        float inv = 1.0f / sum;
        for (int kk = lane; kk < 65; kk += 32)
            S[rr * 65 + kk] = __expf(S[rr * 65 + kk] - mx) * inv;
    }
    __syncthreads();

    for (int idx = tid; idx < 64 * 64; idx += 256) {
        int l = idx >> 6, d = idx & 63;
        const float* sp = S + l * 65;
        const float* vp = Vs + d;
        float s = 0.f;
#pragma unroll
        for (int kk = 0; kk < 65; kk++) s = fmaf(sp[kk], vp[kk * 65], s);
        size_t oi = (bn * 64 + l) * 512 + h * 64 + d;
        __nv_bfloat16 hh = __float2bfloat16(s);
        Oh[oi] = hh;
        Ol[oi] = __float2bfloat16(s - __bfloat162float(hh));
    }
}

// ================= launch =================
extern "C" void kernel_launch(void* const* d_in, const int* in_sizes, int n_in,
                              void* d_out, int out_size) {
    // Bind inputs by element count (all distinct)
    const float *x = 0, *edge = 0, *qkv_w = 0, *qkv_b = 0, *proj_w = 0, *proj_b = 0;
    const void  *mask = 0;
    for (int i = 0; i < n_in; i++) {
        switch (in_sizes[i]) {
            case 33554432: x      = (const float*)d_in[i]; break;
            case 1064960:  mask   = d_in[i];               break;
            case 4259840:  edge   = (const float*)d_in[i]; break;
            case 786432:   qkv_w  = (const float*)d_in[i]; break;
            case 1536:     qkv_b  = (const float*)d_in[i]; break;
            case 262144:   proj_w = (const float*)d_in[i]; break;
            case 512:      proj_b = (const float*)d_in[i]; break;
            default: break;
        }
    }
    float* out = (float*)d_out;

    __nv_bfloat16 *xh, *xl, *bmh, *bml, *wqh, *wql, *wph, *wpl, *Oh, *Ol;
    float *bmean, *Q, *KV;
    cudaGetSymbolAddress((void**)&xh, g_xh);
    cudaGetSymbolAddress((void**)&xl, g_xl);
    cudaGetSymbolAddress((void**)&bmean, g_bmean);
    cudaGetSymbolAddress((void**)&bmh, g_bmh);
    cudaGetSymbolAddress((void**)&bml, g_bml);
    cudaGetSymbolAddress((void**)&wqh, g_wqh);
    cudaGetSymbolAddress((void**)&wql, g_wql);
    cudaGetSymbolAddress((void**)&wph, g_wph);
    cudaGetSymbolAddress((void**)&wpl, g_wpl);
    cudaGetSymbolAddress((void**)&Q,  g_Q);
    cudaGetSymbolAddress((void**)&KV, g_KV);
    cudaGetSymbolAddress((void**)&Oh, g_Oh);
    cudaGetSymbolAddress((void**)&Ol, g_Ol);

    cudaFuncSetAttribute(gemm_mma, cudaFuncAttributeMaxDynamicSharedMemorySize, GEMM_SMEM);
    cudaFuncSetAttribute(attn_kernel, cudaFuncAttributeMaxDynamicSharedMemorySize,
                         ATTN_SMEM_FLOATS * (int)sizeof(float));

    // 0. mask dtype
    detect_mask_kernel<<<1, 256>>>((const unsigned char*)mask);

    // 1. block means + hi/lo splits (weights keep [K][N] layout — no transpose needed)
    block_mean_kernel<<<BB * NBL, CC>>>(x, bmean);
    {
        size_t n = (size_t)BB * NBL * LQ * CC;
        split_kernel<<<(unsigned)((n + 255) / 256), 256>>>(x, xh, xl, n);
    }
    {
        size_t n = (size_t)BB * NBL * CC;
        split_kernel<<<(unsigned)((n + 255) / 256), 256>>>(bmean, bmh, bml, n);
    }
    split_kernel<<<(786432 + 255) / 256, 256>>>(qkv_w, wqh, wql, 786432);
    split_kernel<<<(262144 + 255) / 256, 256>>>(proj_w, wph, wpl, 262144);

    // 2. Q = x @ Wq[:, 0:512] + bq          (M=65536, N=512)
    gemm_mma<<<dim3(512 / 128, 65536 / 128), 256, GEMM_SMEM>>>(
        xh, xl, bmh, bml, 0, wqh, wql, THREE_C, 0, qkv_b, Q, CC);

    // 3. KV = gather(kv) @ Wq[:, 512:1536] + bkv   (M=66560, N=1024)
    gemm_mma<<<dim3(1024 / 128, 66560 / 128), 256, GEMM_SMEM>>>(
        xh, xl, bmh, bml, 1, wqh, wql, THREE_C, 512, qkv_b + 512, KV, 2 * CC);

    // 4. attention -> Oh/Ol (bf16 hi/lo)
    attn_kernel<<<dim3(HH, NBL, BB), 256, ATTN_SMEM_FLOATS * sizeof(float)>>>(
        Q, KV, edge, mask, Oh, Ol);

    // 5. out = O @ Wp + bp        (M=65536, N=512)
    gemm_mma<<<dim3(512 / 128, 65536 / 128), 256, GEMM_SMEM>>>(
        Oh, Ol, bmh, bml, 0, wph, wpl, CC, 0, proj_b, out, CC);
}

// round 10
// speedup vs baseline: 2.0384x; 1.2397x over previous
#include <cuda_runtime.h>
#include <cuda_bf16.h>
#include <cuda_fp16.h>
#include <cstdint>
#include <cstddef>

// Problem constants
#define BB   4
#define NBL  256
#define LQ   64
#define KK_  65
#define CC   512
#define HH   8
#define SCALE 0.125f
#define THREE_C 1536

// ---------------- scratch (static device globals: allocation-free) ----------------
__device__ __align__(128) __half g_xh[(size_t)BB * NBL * LQ * CC];     // 67MB
__device__ __align__(128) __half g_xl[(size_t)BB * NBL * LQ * CC];     // 67MB
__device__ __align__(128) float  g_bmean[(size_t)BB * NBL * CC];       //  2MB
__device__ __align__(128) __half g_bmh[(size_t)BB * NBL * CC];
__device__ __align__(128) __half g_bml[(size_t)BB * NBL * CC];
__device__ __align__(128) __half g_wqh[(size_t)CC * THREE_C];          // [K=512][1536] hi only
__device__ __align__(128) __half g_wph[(size_t)CC * CC];               // [512][512] hi only
__device__ __align__(128) float  g_Q [(size_t)BB * NBL * LQ * CC];     // 134MB
__device__ __align__(128) float  g_KV[(size_t)BB * NBL * KK_ * 2 * CC];// 272MB
__device__ __align__(128) __half g_Oh[(size_t)BB * NBL * LQ * CC];     // 67MB
__device__ __align__(128) __half g_Ol[(size_t)BB * NBL * LQ * CC];     // 67MB
__device__ int g_mask_mode;

// ================= PTX helpers (all baseline compute_80-era, no 'a' features) ===
__device__ __forceinline__ uint32_t smem_u32(const void* p) {
    uint32_t a;
    asm("{ .reg .u64 t; cvta.to.shared.u64 t, %1; cvt.u32.u64 %0, t; }" : "=r"(a) : "l"(p));
    return a;
}
#define CP16(d, s)   asm volatile("cp.async.cg.shared.global [%0], [%1], 16;" :: "r"(d), "l"(s))
#define CP_COMMIT()  asm volatile("cp.async.commit_group;" ::: "memory")
#define CP_WAIT2()   asm volatile("cp.async.wait_group 2;" ::: "memory")

#define LDSM4(d, addr)                                                           \
    asm volatile("ldmatrix.sync.aligned.m8n8.x4.shared.b16 {%0,%1,%2,%3}, [%4];" \
        : "=r"((d)[0]), "=r"((d)[1]), "=r"((d)[2]), "=r"((d)[3]) : "r"(addr))
#define LDSM4T(d, addr)                                                          \
    asm volatile("ldmatrix.sync.aligned.m8n8.x4.trans.shared.b16 {%0,%1,%2,%3}, [%4];" \
        : "=r"((d)[0]), "=r"((d)[1]), "=r"((d)[2]), "=r"((d)[3]) : "r"(addr))

#define MMA16816F16(acc, a, b)                                                   \
    asm volatile("mma.sync.aligned.m16n8k16.row.col.f32.f16.f16.f32 "            \
        "{%0,%1,%2,%3}, {%4,%5,%6,%7}, {%8,%9}, {%0,%1,%2,%3};"                  \
        : "+f"((acc)[0]), "+f"((acc)[1]), "+f"((acc)[2]), "+f"((acc)[3])         \
        : "r"((a)[0]), "r"((a)[1]), "r"((a)[2]), "r"((a)[3]),                    \
          "r"((b)[0]), "r"((b)[1]))

// ================= small kernels =================
__global__ void detect_mask_kernel(const unsigned char* __restrict__ m) {
    __shared__ int sA, s0;
    if (threadIdx.x == 0) { sA = 0; s0 = 0; }
    __syncthreads();
    int a = 0, z = 0;
    for (int i = threadIdx.x; i < 4096; i += blockDim.x) {
        int v = m[i];
        if ((i & 3) == 1) a |= v;
        if ((i & 3) == 0) z |= v;
    }
    if (a) atomicOr(&sA, 1);
    if (z) atomicOr(&s0, 1);
    __syncthreads();
    if (threadIdx.x == 0) g_mask_mode = sA ? 0 : (s0 ? 1 : 2);
}

__global__ void block_mean_kernel(const float* __restrict__ x, float* __restrict__ bm) {
    int blk = blockIdx.x, c = threadIdx.x;
    const float* base = x + (size_t)blk * LQ * CC + c;
    float s = 0.f;
#pragma unroll
    for (int l = 0; l < LQ; l++) s += base[(size_t)l * CC];
    bm[(size_t)blk * CC + c] = s * (1.0f / 64.0f);
}

// fp32 -> fp16 hi + fp16 lo
__global__ void split_kernel(const float* __restrict__ src,
                             __half* __restrict__ dh,
                             __half* __restrict__ dl, size_t n) {
    size_t i = (size_t)blockIdx.x * blockDim.x + threadIdx.x;
    if (i >= n) return;
    float v = src[i];
    __half h = __float2half(v);
    dh[i] = h;
    dl[i] = __float2half(v - __half2float(h));
}

// fp32 -> fp16 hi only (weights)
__global__ void cvt_kernel(const float* __restrict__ src,
                           __half* __restrict__ dh, size_t n) {
    size_t i = (size_t)blockIdx.x * blockDim.x + threadIdx.x;
    if (i >= n) return;
    dh[i] = __float2half(src[i]);
}

// ================= mma.sync fp16 GEMM (2-product compensation) =================
// C[M,N] = (Ah+Al)[M,512] @ Bh[512, wcol0:wcol0+N] + bias
// CTA 128x128, 8 warps (2m x 4n), warp tile 64x32. K chunks of 32, 3-stage cp.async.
#define KCHUNK     32
#define NCHUNK     16                     // 512 / 32
#define A_STRIDE_B 80                     // 40 fp16 per A smem row
#define B_STRIDE_B 272                    // 136 fp16 per B smem row
#define A_HALF     10240                  // 128 * 80
#define B_OFF      20480                  // 2 * A_HALF
#define STAGE_BYTES 29184                 // 2*A_HALF + 32*272
#define GEMM_SMEM  (3 * STAGE_BYTES)      // 87552 -> 2 CTAs/SM

__device__ __forceinline__ void a_ptrs(
    const __half* __restrict__ Ah, const __half* __restrict__ Al,
    const __half* __restrict__ bmh, const __half* __restrict__ bml,
    int gmode, int gr,
    const __half*& ph, const __half*& pl)
{
    if (gmode == 0) { size_t o = (size_t)gr * CC; ph = Ah + o; pl = Al + o; return; }
    int b  = gr / (NBL * KK_);
    int t  = gr - b * (NBL * KK_);
    int nb = t / KK_;
    int kk = t - nb * KK_;
    if (kk < LQ) { size_t o = ((size_t)(b * NBL + nb) * LQ + kk) * CC; ph = Ah + o; pl = Al + o; }
    else         { size_t o = (size_t)(b * NBL + nb) * CC;             ph = bmh + o; pl = bml + o; }
}

__global__ __launch_bounds__(256) void gemm_mma(
    const __half* __restrict__ Ah, const __half* __restrict__ Al,
    const __half* __restrict__ bmh, const __half* __restrict__ bml,
    int gmode,
    const __half* __restrict__ Bh,
    int ldB, int wcol0,
    const float* __restrict__ bias,
    float* __restrict__ C, int ldc)
{
    extern __shared__ __align__(128) char smem[];
    const uint32_t sb = smem_u32(smem);
    const int tid = threadIdx.x, wid = tid >> 5, lane = tid & 31;
    const int warp_m = wid >> 2, warp_n = wid & 3;
    const int rowBase = blockIdx.y * 128;
    const int colBase = blockIdx.x * 128;
    const int colOff  = wcol0 + colBase;
    const int g = lane >> 3, r = lane & 7;

    float acc[4][4][4];
#pragma unroll
    for (int ma = 0; ma < 4; ma++)
#pragma unroll
        for (int na = 0; na < 4; na++)
#pragma unroll
            for (int q = 0; q < 4; q++) acc[ma][na][q] = 0.f;

    const uint32_t aOff = (uint32_t)((warp_m * 64 + (g & 1) * 8 + r) * A_STRIDE_B + (g >> 1) * 16);
    const uint32_t bOff = (uint32_t)(B_OFF + ((g & 1) * 8 + r) * B_STRIDE_B
                                     + (warp_n * 32 + (g >> 1) * 8) * 2);

    auto load_chunk = [&](int k0, uint32_t stBase) {
        // A: 128 rows x 32 fp16 (64B) = 4 x 16B per row, hi & lo
#pragma unroll
        for (int i = tid; i < 512; i += 256) {
            int row = i >> 2, seg = i & 3;
            const __half *ph, *pl;
            a_ptrs(Ah, Al, bmh, bml, gmode, rowBase + row, ph, pl);
            uint32_t da = stBase + row * A_STRIDE_B + seg * 16;
            CP16(da,          ph + k0 + seg * 8);
            CP16(da + A_HALF, pl + k0 + seg * 8);
        }
        // B: 32 rows x 128 fp16 (256B) = 16 x 16B per row, hi only
#pragma unroll
        for (int i = tid; i < 512; i += 256) {
            int row = i >> 4, seg = i & 15;
            size_t off = (size_t)(k0 + row) * ldB + colOff + seg * 8;
            CP16(stBase + B_OFF + row * B_STRIDE_B + seg * 16, Bh + off);
        }
    };

#pragma unroll
    for (int s = 0; s < 3; s++) {
        load_chunk(s * KCHUNK, sb + s * STAGE_BYTES);
        CP_COMMIT();
    }

    for (int c = 0; c < NCHUNK; c++) {
        CP_WAIT2();
        __syncthreads();
        const uint32_t st = sb + (c % 3) * STAGE_BYTES;

#pragma unroll
        for (int ks = 0; ks < 2; ks++) {
            uint32_t ah[4][4], al[4][4], bh[2][4];
#pragma unroll
            for (int ma = 0; ma < 4; ma++) {
                uint32_t ad = st + aOff + ma * (16 * A_STRIDE_B) + ks * 32;
                LDSM4(ah[ma], ad);
                LDSM4(al[ma], ad + A_HALF);
            }
#pragma unroll
            for (int p = 0; p < 2; p++) {
                uint32_t bd = st + bOff + ks * (16 * B_STRIDE_B) + p * 32;
                LDSM4T(bh[p], bd);
            }
#pragma unroll
            for (int ma = 0; ma < 4; ma++)
#pragma unroll
                for (int na = 0; na < 4; na++) {
                    int p = na >> 1, q = (na & 1) * 2;
                    MMA16816F16(acc[ma][na], ah[ma], bh[p] + q);
                    MMA16816F16(acc[ma][na], al[ma], bh[p] + q);
                }
        }
        __syncthreads();
        if (c + 3 < NCHUNK) load_chunk((c + 3) * KCHUNK, st);
        CP_COMMIT();
    }

    // epilogue: direct STG with bias
#pragma unroll
    for (int ma = 0; ma < 4; ma++) {
        int gr = rowBase + warp_m * 64 + ma * 16 + (lane >> 2);
#pragma unroll
        for (int na = 0; na < 4; na++) {
            int gc = colBase + warp_n * 32 + na * 8 + 2 * (lane & 3);
            float b0 = bias[gc], b1 = bias[gc + 1];
            float2 v0 = make_float2(acc[ma][na][0] + b0, acc[ma][na][1] + b1);
            float2 v1 = make_float2(acc[ma][na][2] + b0, acc[ma][na][3] + b1);
            *(float2*)&C[(size_t)gr * ldc + gc]       = v0;
            *(float2*)&C[(size_t)(gr + 8) * ldc + gc] = v1;
        }
    }
}

// ================= fused per-(b,nb,h) attention (fp32, outputs fp16 hi/lo) ========
#define ATTN_SMEM_FLOATS (64 * 64 + 65 * 65 + 65 * 65 + 64 * 65)

__global__ __launch_bounds__(256) void attn_kernel(
    const float* __restrict__ Qb, const float* __restrict__ KVb,
    const float* __restrict__ edge, const void* __restrict__ maskp,
    __half* __restrict__ Oh, __half* __restrict__ Ol)
{
    extern __shared__ float sm[];
    float* Qs = sm;
    float* Ks = Qs + 64 * 64;
    float* Vs = Ks + 65 * 65;
    float* S  = Vs + 65 * 65;

    const int h  = blockIdx.x;
    const int nb = blockIdx.y;
    const int b  = blockIdx.z;
    const int tid = threadIdx.x;
    const size_t bn = (size_t)b * NBL + nb;

    for (int idx = tid; idx < 64 * 64; idx += 256) {
        int l = idx >> 6, d = idx & 63;
        Qs[idx] = Qb[(bn * 64 + l) * 512 + h * 64 + d];
    }
    for (int idx = tid; idx < 65 * 64; idx += 256) {
        int kk = idx >> 6, d = idx & 63;
        size_t rb = (bn * 65 + kk) * 1024 + h * 64 + d;
        Ks[kk * 65 + d] = KVb[rb];
        Vs[kk * 65 + d] = KVb[rb + 512];
    }
    __syncthreads();

    const int mode = g_mask_mode;

    for (int idx = tid; idx < 64 * 65; idx += 256) {
        int l  = idx / 65;
        int kk = idx - l * 65;
        const float* q  = Qs + l * 64;
        const float* kp = Ks + kk * 65;
        float s = 0.f;
#pragma unroll
        for (int d = 0; d < 64; d++) s = fmaf(q[d], kp[d], s);
        s *= SCALE;

        float bias;
        if (kk == 64 || kk == l) bias = 1.0f;
        else bias = edge[((((size_t)nb * 64) + l) * 65 + kk) * 4 + 3];
        s += bias;

        size_t mi = ((size_t)nb * 64 + l) * 65 + kk;
        bool ok;
        if (mode == 0)      ok = ((const unsigned char*)maskp)[mi] != 0;
        else if (mode == 1) ok = ((const int*)maskp)[mi] != 0;
        else                ok = ((const float*)maskp)[mi] != 0.0f;

        S[l * 65 + kk] = ok ? s : -1.0e9f;
    }
    __syncthreads();

    const int w = tid >> 5, lane = tid & 31;
    for (int rr = w; rr < 64; rr += 8) {
        float mx = -1.0e30f;
        for (int kk = lane; kk < 65; kk += 32) mx = fmaxf(mx, S[rr * 65 + kk]);
#pragma unroll
        for (int off = 16; off; off >>= 1) mx = fmaxf(mx, __shfl_xor_sync(0xffffffffu, mx, off));
        float sum = 0.f;
        for (int kk = lane; kk < 65; kk += 32) sum += __expf(S[rr * 65 + kk] - mx);
#pragma unroll
        for (int off = 16; off; off >>= 1) sum += __shfl_xor_sync(0xffffffffu, sum, off);
        float inv = 1.0f / sum;
        for (int kk = lane; kk < 65; kk += 32)
            S[rr * 65 + kk] = __expf(S[rr * 65 + kk] - mx) * inv;
    }
    __syncthreads();

    for (int idx = tid; idx < 64 * 64; idx += 256) {
        int l = idx >> 6, d = idx & 63;
        const float* sp = S + l * 65;
        const float* vp = Vs + d;
        float s = 0.f;
#pragma unroll
        for (int kk = 0; kk < 65; kk++) s = fmaf(sp[kk], vp[kk * 65], s);
        size_t oi = (bn * 64 + l) * 512 + h * 64 + d;
        __half hh = __float2half(s);
        Oh[oi] = hh;
        Ol[oi] = __float2half(s - __half2float(hh));
    }
}

// ================= launch =================
extern "C" void kernel_launch(void* const* d_in, const int* in_sizes, int n_in,
                              void* d_out, int out_size) {
    // Bind inputs by element count (all distinct)
    const float *x = 0, *edge = 0, *qkv_w = 0, *qkv_b = 0, *proj_w = 0, *proj_b = 0;
    const void  *mask = 0;
    for (int i = 0; i < n_in; i++) {
        switch (in_sizes[i]) {
            case 33554432: x      = (const float*)d_in[i]; break;
            case 1064960:  mask   = d_in[i];               break;
            case 4259840:  edge   = (const float*)d_in[i]; break;
            case 786432:   qkv_w  = (const float*)d_in[i]; break;
            case 1536:     qkv_b  = (const float*)d_in[i]; break;
            case 262144:   proj_w = (const float*)d_in[i]; break;
            case 512:      proj_b = (const float*)d_in[i]; break;
            default: break;
        }
    }
    float* out = (float*)d_out;

    __half *xh, *xl, *bmh, *bml, *wqh, *wph, *Oh, *Ol;
    float *bmean, *Q, *KV;
    cudaGetSymbolAddress((void**)&xh, g_xh);
    cudaGetSymbolAddress((void**)&xl, g_xl);
    cudaGetSymbolAddress((void**)&bmean, g_bmean);
    cudaGetSymbolAddress((void**)&bmh, g_bmh);
    cudaGetSymbolAddress((void**)&bml, g_bml);
    cudaGetSymbolAddress((void**)&wqh, g_wqh);
    cudaGetSymbolAddress((void**)&wph, g_wph);
    cudaGetSymbolAddress((void**)&Q,  g_Q);
    cudaGetSymbolAddress((void**)&KV, g_KV);
    cudaGetSymbolAddress((void**)&Oh, g_Oh);
    cudaGetSymbolAddress((void**)&Ol, g_Ol);

    cudaFuncSetAttribute(gemm_mma, cudaFuncAttributeMaxDynamicSharedMemorySize, GEMM_SMEM);
    cudaFuncSetAttribute(attn_kernel, cudaFuncAttributeMaxDynamicSharedMemorySize,
                         ATTN_SMEM_FLOATS * (int)sizeof(float));

    // 0. mask dtype
    detect_mask_kernel<<<1, 256>>>((const unsigned char*)mask);

    // 1. block means + hi/lo splits (weights: hi only)
    block_mean_kernel<<<BB * NBL, CC>>>(x, bmean);
    {
        size_t n = (size_t)BB * NBL * LQ * CC;
        split_kernel<<<(unsigned)((n + 255) / 256), 256>>>(x, xh, xl, n);
    }
    {
        size_t n = (size_t)BB * NBL * CC;
        split_kernel<<<(unsigned)((n + 255) / 256), 256>>>(bmean, bmh, bml, n);
    }
    cvt_kernel<<<(786432 + 255) / 256, 256>>>(qkv_w, wqh, 786432);
    cvt_kernel<<<(262144 + 255) / 256, 256>>>(proj_w, wph, 262144);

    // 2. Q = x @ Wq[:, 0:512] + bq          (M=65536, N=512)
    gemm_mma<<<dim3(512 / 128, 65536 / 128), 256, GEMM_SMEM>>>(
        xh, xl, bmh, bml, 0, wqh, THREE_C, 0, qkv_b, Q, CC);

    // 3. KV = gather(kv) @ Wq[:, 512:1536] + bkv   (M=66560, N=1024)
    gemm_mma<<<dim3(1024 / 128, 66560 / 128), 256, GEMM_SMEM>>>(
        xh, xl, bmh, bml, 1, wqh, THREE_C, 512, qkv_b + 512, KV, 2 * CC);

    // 4. attention -> Oh/Ol (fp16 hi/lo)
    attn_kernel<<<dim3(HH, NBL, BB), 256, ATTN_SMEM_FLOATS * sizeof(float)>>>(
        Q, KV, edge, mask, Oh, Ol);

    // 5. out = O @ Wp + bp        (M=65536, N=512)
    gemm_mma<<<dim3(512 / 128, 65536 / 128), 256, GEMM_SMEM>>>(
        Oh, Ol, bmh, bml, 0, wph, CC, 0, proj_b, out, CC);
}